// round 2
// baseline (speedup 1.0000x reference)
#include <cuda_runtime.h>
#include <cstdint>

static constexpr int HID = 2048;
static constexpr int HV4 = HID / 4;          // 512 float4 per row
static constexpr int NTHREADS = 512;
static constexpr int NWARP = NTHREADS / 32;  // 16
static constexpr int STAGE_F4 = 5 * HV4;     // 5 rows per stage
static constexpr size_t SMEM_BYTES = 2 * STAGE_F4 * sizeof(float4);  // 80 KB

#define CP_ASYNC16(dst_smem_u32, src_gptr) \
    asm volatile("cp.async.cg.shared.global [%0], [%1], 16;\n" \
                 :: "r"(dst_smem_u32), "l"(src_gptr))
#define CP_COMMIT() asm volatile("cp.async.commit_group;\n" ::: "memory")
#define CP_WAIT1()  asm volatile("cp.async.wait_group 1;\n" ::: "memory")

__global__ __launch_bounds__(NTHREADS, 2)
void altup_kernel(const float* __restrict__ hs,    // [4, T, H]
                  const float* __restrict__ act,   // [T, H]
                  const float* __restrict__ rns,   // [H]
                  const float* __restrict__ rw,    // [H, 4]
                  const float* __restrict__ pw,    // [4, 16]
                  const float* __restrict__ cw,    // [4, 4]
                  const float* __restrict__ cosc,  // [H]
                  float* __restrict__ out,         // [4, T, H]
                  int n_tokens)
{
    extern __shared__ float4 buf[];       // [2][5][HV4]
    __shared__ float red[NWARP][10];
    __shared__ float bc[20];              // raw[16], coef[4]

    const int tid  = threadIdx.x;
    const int lane = tid & 31;
    const int warp = tid >> 5;

    // ---- loop-invariant per-thread weights (channels 4*tid .. 4*tid+3) ----
    const float4 rsc = ((const float4*)rns)[tid];
    const float4* rw4 = (const float4*)rw;
    float4 w0 = rw4[4 * tid + 0];
    float4 w1 = rw4[4 * tid + 1];
    float4 w2 = rw4[4 * tid + 2];
    float4 w3 = rw4[4 * tid + 3];
    w0.x *= rsc.x; w0.y *= rsc.x; w0.z *= rsc.x; w0.w *= rsc.x;
    w1.x *= rsc.y; w1.y *= rsc.y; w1.z *= rsc.y; w1.w *= rsc.y;
    w2.x *= rsc.z; w2.y *= rsc.z; w2.z *= rsc.z; w2.w *= rsc.z;
    w3.x *= rsc.w; w3.y *= rsc.w; w3.z *= rsc.w; w3.w *= rsc.w;
    const float4 cs = ((const float4*)cosc)[tid];

    const size_t plane = (size_t)n_tokens * HV4;
    const float4* hsv  = (const float4*)hs;
    const float4* actv = (const float4*)act;
    float4* outv = (float4*)out;

    const uint32_t sbase =
        (uint32_t)__cvta_generic_to_shared(buf) + (uint32_t)(tid * sizeof(float4));
    const uint32_t stage_bytes = STAGE_F4 * sizeof(float4);
    const uint32_t row_bytes   = HV4 * sizeof(float4);

    // ---- prologue: prefetch first token ----
    int t0 = blockIdx.x;
    if (t0 < n_tokens) {
        const float4* g = hsv + (size_t)t0 * HV4 + tid;
        #pragma unroll
        for (int r = 0; r < 4; r++)
            CP_ASYNC16(sbase + r * row_bytes, g + (size_t)r * plane);
        CP_ASYNC16(sbase + 4 * row_bytes, actv + (size_t)t0 * HV4 + tid);
    }
    CP_COMMIT();

    int s = 0;
    for (int t = t0; t < n_tokens; t += gridDim.x) {
        // ---- prefetch next token into the other stage ----
        const int tn = t + gridDim.x;
        if (tn < n_tokens) {
            const uint32_t nb = sbase + (s ^ 1) * stage_bytes;
            const float4* g = hsv + (size_t)tn * HV4 + tid;
            #pragma unroll
            for (int r = 0; r < 4; r++)
                CP_ASYNC16(nb + r * row_bytes, g + (size_t)r * plane);
            CP_ASYNC16(nb + 4 * row_bytes, actv + (size_t)tn * HV4 + tid);
        }
        CP_COMMIT();
        CP_WAIT1();               // current stage resident
        __syncthreads();

        const float4* b = buf + s * STAGE_F4 + tid;
        float4 x0 = b[0];
        float4 x1 = b[HV4];
        float4 x2 = b[2 * HV4];
        float4 x3 = b[3 * HV4];
        float4 a  = b[4 * HV4];

        // ---- 10 per-thread partials ----
        float p[10];
        p[0] = x0.x*x0.x + x0.y*x0.y + x0.z*x0.z + x0.w*x0.w;
        p[1] = a.x*a.x + a.y*a.y + a.z*a.z + a.w*a.w;
        p[2] = x0.x*w0.x + x0.y*w1.x + x0.z*w2.x + x0.w*w3.x;
        p[3] = x0.x*w0.y + x0.y*w1.y + x0.z*w2.y + x0.w*w3.y;
        p[4] = x0.x*w0.z + x0.y*w1.z + x0.z*w2.z + x0.w*w3.z;
        p[5] = x0.x*w0.w + x0.y*w1.w + x0.z*w2.w + x0.w*w3.w;
        p[6] = a.x*w0.x + a.y*w1.x + a.z*w2.x + a.w*w3.x;
        p[7] = a.x*w0.y + a.y*w1.y + a.z*w2.y + a.w*w3.y;
        p[8] = a.x*w0.z + a.y*w1.z + a.z*w2.z + a.w*w3.z;
        p[9] = a.x*w0.w + a.y*w1.w + a.z*w2.w + a.w*w3.w;

        #pragma unroll
        for (int i = 0; i < 10; i++) {
            #pragma unroll
            for (int off = 16; off > 0; off >>= 1)
                p[i] += __shfl_xor_sync(0xffffffffu, p[i], off);
        }
        if (lane == 0) {
            #pragma unroll
            for (int i = 0; i < 10; i++) red[warp][i] = p[i];
        }
        __syncthreads();

        // ---- parallel tail: warp 0 only ----
        if (warp == 0) {
            float v = 0.0f;
            if (lane < 10) {
                #pragma unroll
                for (int w = 0; w < NWARP; w++) v += red[w][lane];
            }
            const float s0 = __shfl_sync(0xffffffffu, v, 0);
            const float s1 = __shfl_sync(0xffffffffu, v, 1);
            float sp[4], sc[4];
            #pragma unroll
            for (int n = 0; n < 4; n++) {
                sp[n] = __shfl_sync(0xffffffffu, v, 2 + n);
                sc[n] = __shfl_sync(0xffffffffu, v, 6 + n);
            }
            const float invH = 1.0f / (float)HID;
            const float ih = rsqrtf(s0 * invH + 1e-6f) * invH;
            const float ia = rsqrtf(s1 * invH + 1e-6f) * invH;
            float mp[4], mc[4];
            #pragma unroll
            for (int n = 0; n < 4; n++) {
                mp[n] = tanhf(sp[n] * ih);
                mc[n] = tanhf(sc[n] * ia);
            }
            if (lane < 16) {
                float r = mp[0] * pw[lane] + mp[1] * pw[16 + lane]
                        + mp[2] * pw[32 + lane] + mp[3] * pw[48 + lane];
                bc[lane] = r;
            } else if (lane < 20) {
                const int m = lane - 16;
                float c = 1.0f + mc[0] * cw[m] + mc[1] * cw[4 + m]
                               + mc[2] * cw[8 + m] + mc[3] * cw[12 + m];
                bc[lane] = c;
            }
        }
        __syncthreads();

        // ---- phase 2: mix, innovate, correct, scale, store ----
        const size_t tb = (size_t)t * HV4 + tid;
        float r00 = bc[0], r01 = bc[1], r02 = bc[2], r03 = bc[3];
        float4 p0;
        p0.x = x0.x + r00*x0.x + r01*x1.x + r02*x2.x + r03*x3.x;
        p0.y = x0.y + r00*x0.y + r01*x1.y + r02*x2.y + r03*x3.y;
        p0.z = x0.z + r00*x0.z + r01*x1.z + r02*x2.z + r03*x3.z;
        p0.w = x0.w + r00*x0.w + r01*x1.w + r02*x2.w + r03*x3.w;
        float4 inn;
        inn.x = a.x - p0.x; inn.y = a.y - p0.y; inn.z = a.z - p0.z; inn.w = a.w - p0.w;

        {
            const float c = bc[16];
            float4 o;
            o.x = (p0.x + c * inn.x) * cs.x;
            o.y = (p0.y + c * inn.y) * cs.y;
            o.z = (p0.z + c * inn.z) * cs.z;
            o.w = (p0.w + c * inn.w) * cs.w;
            outv[tb] = o;
        }
        #pragma unroll
        for (int m = 1; m < 4; m++) {
            const float rm0 = bc[m*4+0], rm1 = bc[m*4+1], rm2 = bc[m*4+2], rm3 = bc[m*4+3];
            const float c = bc[16 + m];
            float4 xm = (m == 1) ? x1 : ((m == 2) ? x2 : x3);
            float4 pm, o;
            pm.x = xm.x + rm0*x0.x + rm1*x1.x + rm2*x2.x + rm3*x3.x;
            pm.y = xm.y + rm0*x0.y + rm1*x1.y + rm2*x2.y + rm3*x3.y;
            pm.z = xm.z + rm0*x0.z + rm1*x1.z + rm2*x2.z + rm3*x3.z;
            pm.w = xm.w + rm0*x0.w + rm1*x1.w + rm2*x2.w + rm3*x3.w;
            o.x = (pm.x + c * inn.x) * cs.x;
            o.y = (pm.y + c * inn.y) * cs.y;
            o.z = (pm.z + c * inn.z) * cs.z;
            o.w = (pm.w + c * inn.w) * cs.w;
            outv[(size_t)m * plane + tb] = o;
        }
        s ^= 1;
    }
}

extern "C" void kernel_launch(void* const* d_in, const int* in_sizes, int n_in,
                              void* d_out, int out_size) {
    const float* hs   = (const float*)d_in[0];
    const float* act  = (const float*)d_in[1];
    const float* rns  = (const float*)d_in[2];
    const float* rw   = (const float*)d_in[3];
    const float* pw   = (const float*)d_in[4];
    const float* cw   = (const float*)d_in[5];
    const float* cosc = (const float*)d_in[6];
    float* out = (float*)d_out;

    const int n_tokens = in_sizes[1] / HID;

    cudaFuncSetAttribute(altup_kernel,
                         cudaFuncAttributeMaxDynamicSharedMemorySize,
                         (int)SMEM_BYTES);

    const int grid = 304;   // 2 CTAs/SM on 152 SMs, single wave
    altup_kernel<<<grid, NTHREADS, SMEM_BYTES>>>(hs, act, rns, rw, pw, cw, cosc,
                                                 out, n_tokens);
}

// round 3
// speedup vs baseline: 1.1752x; 1.1752x over previous
#include <cuda_runtime.h>
#include <cstdint>

static constexpr int HID = 2048;
static constexpr int HV4 = HID / 4;          // 512 float4 per row
static constexpr int NTHREADS = 512;
static constexpr int NWARP = NTHREADS / 32;  // 16
static constexpr int RPAD = NWARP + 1;       // 17: conflict-free stride

__global__ __launch_bounds__(NTHREADS, 2)
void altup_kernel(const float* __restrict__ hs,    // [4, T, H]
                  const float* __restrict__ act,   // [T, H]
                  const float* __restrict__ rns,   // [H]
                  const float* __restrict__ rw,    // [H, 4]
                  const float* __restrict__ pw,    // [4, 16]
                  const float* __restrict__ cw,    // [4, 4]
                  const float* __restrict__ cosc,  // [H]
                  float* __restrict__ out,         // [4, T, H]
                  int n_tokens)
{
    __shared__ float red[2][10][RPAD];

    const int tid  = threadIdx.x;
    const int lane = tid & 31;
    const int warp = tid >> 5;

    // ---- loop-invariant per-thread router weights (channels 4*tid..4*tid+3) ----
    const float4 rsc = ((const float4*)rns)[tid];
    const float4* rw4 = (const float4*)rw;
    float4 w0 = rw4[4 * tid + 0];
    float4 w1 = rw4[4 * tid + 1];
    float4 w2 = rw4[4 * tid + 2];
    float4 w3 = rw4[4 * tid + 3];
    w0.x *= rsc.x; w0.y *= rsc.x; w0.z *= rsc.x; w0.w *= rsc.x;
    w1.x *= rsc.y; w1.y *= rsc.y; w1.z *= rsc.y; w1.w *= rsc.y;
    w2.x *= rsc.z; w2.y *= rsc.z; w2.z *= rsc.z; w2.w *= rsc.z;
    w3.x *= rsc.w; w3.y *= rsc.w; w3.z *= rsc.w; w3.w *= rsc.w;
    const float4 cs = ((const float4*)cosc)[tid];

    // per-lane coefficient column: lanes 0-15 -> pw[:,lane], lanes 16-19 -> cw[:,lane-16]
    float pv0 = 0.f, pv1 = 0.f, pv2 = 0.f, pv3 = 0.f;
    if (lane < 16) {
        pv0 = pw[lane]; pv1 = pw[16 + lane]; pv2 = pw[32 + lane]; pv3 = pw[48 + lane];
    } else if (lane < 20) {
        const int m = lane - 16;
        pv0 = cw[m]; pv1 = cw[4 + m]; pv2 = cw[8 + m]; pv3 = cw[12 + m];
    }

    const size_t plane = (size_t)n_tokens * HV4;
    const float4* hsv  = (const float4*)hs;
    const float4* actv = (const float4*)act;
    float4* outv = (float4*)out;

    // ---- prologue: prefetch first token's x0 / act ----
    const int t0 = blockIdx.x;
    float4 pre_x0 = make_float4(0.f, 0.f, 0.f, 0.f);
    float4 pre_a  = pre_x0;
    if (t0 < n_tokens) {
        const size_t tb0 = (size_t)t0 * HV4 + tid;
        pre_x0 = hsv[tb0];
        pre_a  = actv[tb0];
    }

    int par = 0;
    for (int t = t0; t < n_tokens; t += gridDim.x) {
        const size_t tb = (size_t)t * HV4 + tid;
        const float4 x0 = pre_x0;
        const float4 a  = pre_a;
        // x1..x3 consumed only after the barrier — latency self-hiding
        float4 x1 = hsv[plane + tb];
        float4 x2 = hsv[2 * plane + tb];
        float4 x3 = hsv[3 * plane + tb];

        // ---- 10 per-thread partials ----
        float p[10];
        p[0] = x0.x*x0.x + x0.y*x0.y + x0.z*x0.z + x0.w*x0.w;
        p[1] = a.x*a.x + a.y*a.y + a.z*a.z + a.w*a.w;
        p[2] = x0.x*w0.x + x0.y*w1.x + x0.z*w2.x + x0.w*w3.x;
        p[3] = x0.x*w0.y + x0.y*w1.y + x0.z*w2.y + x0.w*w3.y;
        p[4] = x0.x*w0.z + x0.y*w1.z + x0.z*w2.z + x0.w*w3.z;
        p[5] = x0.x*w0.w + x0.y*w1.w + x0.z*w2.w + x0.w*w3.w;
        p[6] = a.x*w0.x + a.y*w1.x + a.z*w2.x + a.w*w3.x;
        p[7] = a.x*w0.y + a.y*w1.y + a.z*w2.y + a.w*w3.y;
        p[8] = a.x*w0.z + a.y*w1.z + a.z*w2.z + a.w*w3.z;
        p[9] = a.x*w0.w + a.y*w1.w + a.z*w2.w + a.w*w3.w;

        #pragma unroll
        for (int i = 0; i < 10; i++) {
            #pragma unroll
            for (int off = 16; off > 0; off >>= 1)
                p[i] += __shfl_xor_sync(0xffffffffu, p[i], off);
        }
        if (lane < 10) red[par][lane][warp] = p[lane];

        // ---- prefetch next token's x0 / act (hidden under barrier+tail+stores) ----
        const int tn = t + gridDim.x;
        if (tn < n_tokens) {
            const size_t tnb = (size_t)tn * HV4 + tid;
            pre_x0 = hsv[tnb];
            pre_a  = actv[tnb];
        }

        __syncthreads();   // the ONLY barrier per token

        // ---- redundant per-warp tail (no second barrier) ----
        float v = 0.f;
        if (lane < 10) {
            #pragma unroll
            for (int w = 0; w < NWARP; w++) v += red[par][lane][w];
        }
        const float ssq0 = __shfl_sync(0xffffffffu, v, 0);
        const float ssq1 = __shfl_sync(0xffffffffu, v, 1);
        const float invH = 1.0f / (float)HID;
        const float ih = rsqrtf(ssq0 * invH + 1e-6f) * invH;
        const float ia = rsqrtf(ssq1 * invH + 1e-6f) * invH;

        // lanes 0-3 compute tanh(router_p), lanes 4-7 tanh(router_c)
        const float argp = __shfl_sync(0xffffffffu, v, 2 + (lane & 3));
        const float argc = __shfl_sync(0xffffffffu, v, 6 + (lane & 3));
        const float tv = tanhf((lane < 4) ? argp * ih : argc * ia);

        float mp[4], mc[4];
        #pragma unroll
        for (int k = 0; k < 4; k++) {
            mp[k] = __shfl_sync(0xffffffffu, tv, k);
            mc[k] = __shfl_sync(0xffffffffu, tv, 4 + k);
        }
        const float m0 = (lane < 16) ? mp[0] : mc[0];
        const float m1 = (lane < 16) ? mp[1] : mc[1];
        const float m2 = (lane < 16) ? mp[2] : mc[2];
        const float m3 = (lane < 16) ? mp[3] : mc[3];
        const float val = ((lane < 16) ? 0.f : 1.f)
                        + m0 * pv0 + m1 * pv1 + m2 * pv2 + m3 * pv3;

        // broadcast the 20 scalars
        float r00 = __shfl_sync(0xffffffffu, val, 0);
        float r01 = __shfl_sync(0xffffffffu, val, 1);
        float r02 = __shfl_sync(0xffffffffu, val, 2);
        float r03 = __shfl_sync(0xffffffffu, val, 3);
        float c0  = __shfl_sync(0xffffffffu, val, 16);

        // ---- phase 2: mix, innovate, correct, scale, store ----
        float4 p0;
        p0.x = x0.x + r00*x0.x + r01*x1.x + r02*x2.x + r03*x3.x;
        p0.y = x0.y + r00*x0.y + r01*x1.y + r02*x2.y + r03*x3.y;
        p0.z = x0.z + r00*x0.z + r01*x1.z + r02*x2.z + r03*x3.z;
        p0.w = x0.w + r00*x0.w + r01*x1.w + r02*x2.w + r03*x3.w;
        float4 inn;
        inn.x = a.x - p0.x; inn.y = a.y - p0.y; inn.z = a.z - p0.z; inn.w = a.w - p0.w;

        {
            float4 o;
            o.x = (p0.x + c0 * inn.x) * cs.x;
            o.y = (p0.y + c0 * inn.y) * cs.y;
            o.z = (p0.z + c0 * inn.z) * cs.z;
            o.w = (p0.w + c0 * inn.w) * cs.w;
            __stcs(&outv[tb], o);
        }
        #pragma unroll
        for (int m = 1; m < 4; m++) {
            const float rm0 = __shfl_sync(0xffffffffu, val, m * 4 + 0);
            const float rm1 = __shfl_sync(0xffffffffu, val, m * 4 + 1);
            const float rm2 = __shfl_sync(0xffffffffu, val, m * 4 + 2);
            const float rm3 = __shfl_sync(0xffffffffu, val, m * 4 + 3);
            const float cm  = __shfl_sync(0xffffffffu, val, 16 + m);
            const float4 xm = (m == 1) ? x1 : ((m == 2) ? x2 : x3);
            float4 pm, o;
            pm.x = xm.x + rm0*x0.x + rm1*x1.x + rm2*x2.x + rm3*x3.x;
            pm.y = xm.y + rm0*x0.y + rm1*x1.y + rm2*x2.y + rm3*x3.y;
            pm.z = xm.z + rm0*x0.z + rm1*x1.z + rm2*x2.z + rm3*x3.z;
            pm.w = xm.w + rm0*x0.w + rm1*x1.w + rm2*x2.w + rm3*x3.w;
            o.x = (pm.x + cm * inn.x) * cs.x;
            o.y = (pm.y + cm * inn.y) * cs.y;
            o.z = (pm.z + cm * inn.z) * cs.z;
            o.w = (pm.w + cm * inn.w) * cs.w;
            __stcs(&outv[(size_t)m * plane + tb], o);
        }
        par ^= 1;
    }
}

extern "C" void kernel_launch(void* const* d_in, const int* in_sizes, int n_in,
                              void* d_out, int out_size) {
    const float* hs   = (const float*)d_in[0];
    const float* act  = (const float*)d_in[1];
    const float* rns  = (const float*)d_in[2];
    const float* rw   = (const float*)d_in[3];
    const float* pw   = (const float*)d_in[4];
    const float* cw   = (const float*)d_in[5];
    const float* cosc = (const float*)d_in[6];
    float* out = (float*)d_out;

    const int n_tokens = in_sizes[1] / HID;
    const int grid = 304;   // 2 CTAs/SM on 152 SMs, single wave
    altup_kernel<<<grid, NTHREADS>>>(hs, act, rns, rw, pw, cw, cosc, out, n_tokens);
}

// round 4
// speedup vs baseline: 1.2127x; 1.0319x over previous
#include <cuda_runtime.h>
#include <cstdint>

static constexpr int HID = 2048;
static constexpr int HV4 = HID / 4;          // 512 float4 per row
static constexpr int NTHREADS = 512;
static constexpr int NWARP = NTHREADS / 32;  // 16
static constexpr int RPAD = NWARP + 1;       // 17: conflict-free stride

__device__ __forceinline__ float tanh_fast(float x) {
    float r;
    asm("tanh.approx.f32 %0, %1;" : "=f"(r) : "f"(x));
    return r;
}

__global__ __launch_bounds__(NTHREADS, 2)
void altup_kernel(const float* __restrict__ hs,    // [4, T, H]
                  const float* __restrict__ act,   // [T, H]
                  const float* __restrict__ rns,   // [H]
                  const float* __restrict__ rw,    // [H, 4]
                  const float* __restrict__ pw,    // [4, 16]
                  const float* __restrict__ cw,    // [4, 4]
                  const float* __restrict__ cosc,  // [H]
                  float* __restrict__ out,         // [4, T, H]
                  int n_tokens)
{
    __shared__ float4 wsm[4][NTHREADS];      // folded router weights (32 KB)
    __shared__ float red[2][10][RPAD];

    const int tid  = threadIdx.x;
    const int lane = tid & 31;
    const int warp = tid >> 5;

    // ---- prologue: fold rns into rw, park in SMEM ----
    {
        const float4 rsc = ((const float4*)rns)[tid];
        const float4* rw4 = (const float4*)rw;
        float4 w0 = rw4[4 * tid + 0];
        float4 w1 = rw4[4 * tid + 1];
        float4 w2 = rw4[4 * tid + 2];
        float4 w3 = rw4[4 * tid + 3];
        w0.x *= rsc.x; w0.y *= rsc.x; w0.z *= rsc.x; w0.w *= rsc.x;
        w1.x *= rsc.y; w1.y *= rsc.y; w1.z *= rsc.y; w1.w *= rsc.y;
        w2.x *= rsc.z; w2.y *= rsc.z; w2.z *= rsc.z; w2.w *= rsc.z;
        w3.x *= rsc.w; w3.y *= rsc.w; w3.z *= rsc.w; w3.w *= rsc.w;
        wsm[0][tid] = w0; wsm[1][tid] = w1; wsm[2][tid] = w2; wsm[3][tid] = w3;
    }
    const float4 cs = ((const float4*)cosc)[tid];

    // per-lane coefficient column: lanes 0-15 -> pw[:,lane], 16-19 -> cw[:,lane-16]
    float pv0 = 0.f, pv1 = 0.f, pv2 = 0.f, pv3 = 0.f;
    if (lane < 16) {
        pv0 = pw[lane]; pv1 = pw[16 + lane]; pv2 = pw[32 + lane]; pv3 = pw[48 + lane];
    } else if (lane < 20) {
        const int m = lane - 16;
        pv0 = cw[m]; pv1 = cw[4 + m]; pv2 = cw[8 + m]; pv3 = cw[12 + m];
    }

    const size_t plane = (size_t)n_tokens * HV4;
    const float4* hsv  = (const float4*)hs;
    const float4* actv = (const float4*)act;
    float4* outv = (float4*)out;

    // ---- prefetch first token (all 5 rows) ----
    const int t0 = blockIdx.x;
    float4 n0, n1, n2, n3, n4;
    n0 = n1 = n2 = n3 = n4 = make_float4(0.f, 0.f, 0.f, 0.f);
    if (t0 < n_tokens) {
        const size_t tb0 = (size_t)t0 * HV4 + tid;
        n0 = __ldcs(hsv + tb0);
        n1 = __ldcs(hsv + plane + tb0);
        n2 = __ldcs(hsv + 2 * plane + tb0);
        n3 = __ldcs(hsv + 3 * plane + tb0);
        n4 = __ldcs(actv + tb0);
    }
    __syncthreads();   // wsm visible

    int par = 0;
    for (int t = t0; t < n_tokens; t += gridDim.x) {
        const size_t tb = (size_t)t * HV4 + tid;
        const float4 x0 = n0, x1 = n1, x2 = n2, x3 = n3, a = n4;

        // ---- 10 per-thread partials (weights from SMEM) ----
        const float4 w0 = wsm[0][tid];
        const float4 w1 = wsm[1][tid];
        const float4 w2 = wsm[2][tid];
        const float4 w3 = wsm[3][tid];
        float p[10];
        p[0] = x0.x*x0.x + x0.y*x0.y + x0.z*x0.z + x0.w*x0.w;
        p[1] = a.x*a.x + a.y*a.y + a.z*a.z + a.w*a.w;
        p[2] = x0.x*w0.x + x0.y*w1.x + x0.z*w2.x + x0.w*w3.x;
        p[3] = x0.x*w0.y + x0.y*w1.y + x0.z*w2.y + x0.w*w3.y;
        p[4] = x0.x*w0.z + x0.y*w1.z + x0.z*w2.z + x0.w*w3.z;
        p[5] = x0.x*w0.w + x0.y*w1.w + x0.z*w2.w + x0.w*w3.w;
        p[6] = a.x*w0.x + a.y*w1.x + a.z*w2.x + a.w*w3.x;
        p[7] = a.x*w0.y + a.y*w1.y + a.z*w2.y + a.w*w3.y;
        p[8] = a.x*w0.z + a.y*w1.z + a.z*w2.z + a.w*w3.z;
        p[9] = a.x*w0.w + a.y*w1.w + a.z*w2.w + a.w*w3.w;

        #pragma unroll
        for (int i = 0; i < 10; i++) {
            #pragma unroll
            for (int off = 16; off > 0; off >>= 1)
                p[i] += __shfl_xor_sync(0xffffffffu, p[i], off);
        }
        if (lane < 10) red[par][lane][warp] = p[lane];

        // ---- prefetch ALL of next token (hidden under barrier+tail+phase2) ----
        const int tn = t + gridDim.x;
        if (tn < n_tokens) {
            const size_t tnb = (size_t)tn * HV4 + tid;
            n0 = __ldcs(hsv + tnb);
            n1 = __ldcs(hsv + plane + tnb);
            n2 = __ldcs(hsv + 2 * plane + tnb);
            n3 = __ldcs(hsv + 3 * plane + tnb);
            n4 = __ldcs(actv + tnb);
        }

        __syncthreads();   // the ONLY barrier per token

        // ---- redundant per-warp tail ----
        float v = 0.f;
        if (lane < 10) {
            #pragma unroll
            for (int w = 0; w < NWARP; w++) v += red[par][lane][w];
        }
        const float ssq0 = __shfl_sync(0xffffffffu, v, 0);
        const float ssq1 = __shfl_sync(0xffffffffu, v, 1);
        const float invH = 1.0f / (float)HID;
        const float ih = rsqrtf(ssq0 * invH + 1e-6f) * invH;
        const float ia = rsqrtf(ssq1 * invH + 1e-6f) * invH;

        const float argp = __shfl_sync(0xffffffffu, v, 2 + (lane & 3));
        const float argc = __shfl_sync(0xffffffffu, v, 6 + (lane & 3));
        const float tv = tanh_fast((lane < 4) ? argp * ih : argc * ia);

        float mp0 = __shfl_sync(0xffffffffu, tv, 0);
        float mp1 = __shfl_sync(0xffffffffu, tv, 1);
        float mp2 = __shfl_sync(0xffffffffu, tv, 2);
        float mp3 = __shfl_sync(0xffffffffu, tv, 3);
        float mc0 = __shfl_sync(0xffffffffu, tv, 4);
        float mc1 = __shfl_sync(0xffffffffu, tv, 5);
        float mc2 = __shfl_sync(0xffffffffu, tv, 6);
        float mc3 = __shfl_sync(0xffffffffu, tv, 7);
        const float m0 = (lane < 16) ? mp0 : mc0;
        const float m1 = (lane < 16) ? mp1 : mc1;
        const float m2 = (lane < 16) ? mp2 : mc2;
        const float m3 = (lane < 16) ? mp3 : mc3;
        const float val = ((lane < 16) ? 0.f : 1.f)
                        + m0 * pv0 + m1 * pv1 + m2 * pv2 + m3 * pv3;

        const float r00 = __shfl_sync(0xffffffffu, val, 0);
        const float r01 = __shfl_sync(0xffffffffu, val, 1);
        const float r02 = __shfl_sync(0xffffffffu, val, 2);
        const float r03 = __shfl_sync(0xffffffffu, val, 3);
        const float c0  = __shfl_sync(0xffffffffu, val, 16);

        // ---- phase 2: mix, innovate, correct, scale, store ----
        float4 p0;
        p0.x = x0.x + r00*x0.x + r01*x1.x + r02*x2.x + r03*x3.x;
        p0.y = x0.y + r00*x0.y + r01*x1.y + r02*x2.y + r03*x3.y;
        p0.z = x0.z + r00*x0.z + r01*x1.z + r02*x2.z + r03*x3.z;
        p0.w = x0.w + r00*x0.w + r01*x1.w + r02*x2.w + r03*x3.w;
        float4 inn;
        inn.x = a.x - p0.x; inn.y = a.y - p0.y; inn.z = a.z - p0.z; inn.w = a.w - p0.w;

        {
            float4 o;
            o.x = (p0.x + c0 * inn.x) * cs.x;
            o.y = (p0.y + c0 * inn.y) * cs.y;
            o.z = (p0.z + c0 * inn.z) * cs.z;
            o.w = (p0.w + c0 * inn.w) * cs.w;
            __stcs(&outv[tb], o);
        }
        #pragma unroll
        for (int m = 1; m < 4; m++) {
            const float rm0 = __shfl_sync(0xffffffffu, val, m * 4 + 0);
            const float rm1 = __shfl_sync(0xffffffffu, val, m * 4 + 1);
            const float rm2 = __shfl_sync(0xffffffffu, val, m * 4 + 2);
            const float rm3 = __shfl_sync(0xffffffffu, val, m * 4 + 3);
            const float cm  = __shfl_sync(0xffffffffu, val, 16 + m);
            const float4 xm = (m == 1) ? x1 : ((m == 2) ? x2 : x3);
            float4 pm, o;
            pm.x = xm.x + rm0*x0.x + rm1*x1.x + rm2*x2.x + rm3*x3.x;
            pm.y = xm.y + rm0*x0.y + rm1*x1.y + rm2*x2.y + rm3*x3.y;
            pm.z = xm.z + rm0*x0.z + rm1*x1.z + rm2*x2.z + rm3*x3.z;
            pm.w = xm.w + rm0*x0.w + rm1*x1.w + rm2*x2.w + rm3*x3.w;
            o.x = (pm.x + cm * inn.x) * cs.x;
            o.y = (pm.y + cm * inn.y) * cs.y;
            o.z = (pm.z + cm * inn.z) * cs.z;
            o.w = (pm.w + cm * inn.w) * cs.w;
            __stcs(&outv[(size_t)m * plane + tb], o);
        }
        par ^= 1;
    }
}

extern "C" void kernel_launch(void* const* d_in, const int* in_sizes, int n_in,
                              void* d_out, int out_size) {
    const float* hs   = (const float*)d_in[0];
    const float* act  = (const float*)d_in[1];
    const float* rns  = (const float*)d_in[2];
    const float* rw   = (const float*)d_in[3];
    const float* pw   = (const float*)d_in[4];
    const float* cw   = (const float*)d_in[5];
    const float* cosc = (const float*)d_in[6];
    float* out = (float*)d_out;

    const int n_tokens = in_sizes[1] / HID;
    const int grid = 304;   // 2 CTAs/SM on 152 SMs, single wave
    altup_kernel<<<grid, NTHREADS>>>(hs, act, rns, rw, pw, cw, cosc, out, n_tokens);
}